// round 2
// baseline (speedup 1.0000x reference)
#include <cuda_runtime.h>

// VQ-VAE forward on GB300.
// Outputs (flattened, in order): recon (32,3,128,128), z_e (32,512,32,32), emb (32,512,32,32)

#define NB 32
#define NC 3
#define NH 128
#define ND 512
#define NK 512
#define NHL 32
#define NL 1024
#define NM (NB * NL)  // 32768

#define RECON_N (32 * 3 * 128 * 128)       // 1572864
#define ZE_N (32 * 512 * 32 * 32)          // 16777216

// ---------------- scratch (static device memory; no allocations) ----------------
__device__ float g_zt[NM * ND];     // z_e transposed: (M, D) row-major, M = b*1024 + hl*32 + wl
__device__ float g_cbt[NK * ND];    // codebook transposed: (K, D) row-major
__device__ float g_w2[NK];          // ||W[:,k]||^2
__device__ float g_wdt[48 * ND];    // decoder weights: [(c*4+i)*4+j][d], spatial flip baked in
__device__ int   g_idx[NM];         // argmin indices

// ---------------- prep kernels ----------------

// Transpose codebook (D,K) -> (K,D)
__global__ void k_prep_cbt(const float* __restrict__ cb) {
    __shared__ float t[32][33];
    int x = blockIdx.x * 32 + threadIdx.x;   // k
    int y0 = blockIdx.y * 32;                // d base
    for (int r = threadIdx.y; r < 32; r += 8)
        t[r][threadIdx.x] = cb[(y0 + r) * NK + x];
    __syncthreads();
    int xo = blockIdx.y * 32 + threadIdx.x;  // d
    int yo = blockIdx.x * 32;                // k base
    for (int r = threadIdx.y; r < 32; r += 8)
        g_cbt[(yo + r) * ND + xo] = t[threadIdx.x][r];
}

// w2[k] = sum_d cb[d][k]^2  (reads transposed rows)
__global__ void k_prep_w2() {
    int k = blockIdx.x * 128 + threadIdx.x;
    const float* row = g_cbt + k * ND;
    float s = 0.f;
    for (int d = 0; d < ND; d += 4) {
        float4 v = *reinterpret_cast<const float4*>(row + d);
        s += v.x * v.x + v.y * v.y + v.z * v.z + v.w * v.w;
    }
    g_w2[k] = s;
}

// Wd (C,D,4,4) -> g_wdt[(c*4+i)*4+j][d] with spatial FLIP (conv_transpose semantics:
// out[4hl+i,4wl+j] uses Wd[c,d,3-i,3-j] for VALID, stride=kernel=4, no kernel flip flag)
__global__ void k_prep_wdt(const float* __restrict__ Wd) {
    int e = blockIdx.x * 256 + threadIdx.x;  // e < 48*512
    int r = e >> 9;        // (c*4+i)*4+j
    int d = e & 511;
    int c = r >> 4;
    int i = (r >> 2) & 3;
    int j = r & 3;
    g_wdt[e] = Wd[(c * ND + d) * 16 + (3 - i) * 4 + (3 - j)];
}

// ---------------- encode: patch-embed GEMM + bias + relu ----------------
// grid = 1024 (b,hl), 512 threads, thread d = tid.
__global__ __launch_bounds__(512) void k_encode(const float* __restrict__ x,
                                                const float* __restrict__ We,
                                                const float* __restrict__ be,
                                                float* __restrict__ out_ze) {
    __shared__ float patch[32 * 48];  // [pos][c*16+i*4+j]
    int blk = blockIdx.x;
    int b = blk >> 5;
    int hl = blk & 31;
    int tid = threadIdx.x;

    // stage the 12 input rows (3 ch x 4 rows x 128 cols) into per-position patches
    for (int e = tid; e < 1536; e += 512) {
        int row = e >> 7;      // c*4+i
        int col = e & 127;
        int c = row >> 2, i = row & 3;
        float v = x[((b * NC + c) * NH + (4 * hl + i)) * NH + col];
        int pos = col >> 2, j = col & 3;
        patch[pos * 48 + c * 16 + i * 4 + j] = v;
    }

    int d = tid;
    float w[48];
    const float4* wsrc = reinterpret_cast<const float4*>(We + d * 48);
#pragma unroll
    for (int q = 0; q < 12; q++) {
        float4 t = wsrc[q];
        w[4 * q] = t.x; w[4 * q + 1] = t.y; w[4 * q + 2] = t.z; w[4 * q + 3] = t.w;
    }
    float bias = be[d];
    __syncthreads();

    float acc[32];
    int zt_base = (b * NL + hl * 32) * ND + d;
#pragma unroll
    for (int pos = 0; pos < 32; pos++) {
        float v = bias;
        const float4* p4 = reinterpret_cast<const float4*>(patch + pos * 48);
#pragma unroll
        for (int q = 0; q < 12; q++) {
            float4 t = p4[q];
            v += t.x * w[4 * q] + t.y * w[4 * q + 1] + t.z * w[4 * q + 2] + t.w * w[4 * q + 3];
        }
        v = fmaxf(v, 0.f);
        acc[pos] = v;
        g_zt[zt_base + pos * ND] = v;  // coalesced across threads (d contiguous)
    }
    // z_e output (B,D,HL,WL): per-thread contiguous 128B row
    float4* o4 = reinterpret_cast<float4*>(out_ze + ((b * ND + d) * NHL + hl) * NHL);
#pragma unroll
    for (int q = 0; q < 8; q++)
        o4[q] = make_float4(acc[4 * q], acc[4 * q + 1], acc[4 * q + 2], acc[4 * q + 3]);
}

// ---------------- argmin: fp32 GEMM (M,512)x(512,512) + rowwise argmin ----------------
__device__ __forceinline__ unsigned long long packkey(float dist, int k) {
    unsigned u = __float_as_uint(dist);
    u = (u & 0x80000000u) ? ~u : (u | 0x80000000u);  // order-preserving map
    return ((unsigned long long)u << 32) | (unsigned)k;
}

// grid = 512 (row tiles of 64), 256 threads (16x16), thread tile 4x4, BK=16, 8 col chunks of 64.
__global__ __launch_bounds__(256) void k_argmin(const float* __restrict__ cb) {
    __shared__ float a_s[16][65];   // [d][m], padded
    __shared__ float b_s[16][64];   // [d][k]
    __shared__ unsigned long long keys[64];

    int m0 = blockIdx.x * 64;
    int tid = threadIdx.x;
    int tx = tid & 15, ty = tid >> 4;
    if (tid < 64) keys[tid] = 0xFFFFFFFFFFFFFFFFull;

    int lm = tid >> 2;             // A-load row 0..63
    int ldg = (tid & 3) << 2;      // A-load d group
    int ldd = tid >> 4;            // B-load d 0..15
    int lcg = (tid & 15) << 2;     // B-load col group

    for (int nc = 0; nc < 8; nc++) {
        float acc[4][4] = {};
        for (int kt = 0; kt < 32; kt++) {
            float4 av = *reinterpret_cast<const float4*>(&g_zt[(m0 + lm) * ND + kt * 16 + ldg]);
            a_s[ldg + 0][lm] = av.x; a_s[ldg + 1][lm] = av.y;
            a_s[ldg + 2][lm] = av.z; a_s[ldg + 3][lm] = av.w;
            float4 bv = *reinterpret_cast<const float4*>(&cb[(kt * 16 + ldd) * NK + nc * 64 + lcg]);
            *reinterpret_cast<float4*>(&b_s[ldd][lcg]) = bv;
            __syncthreads();
#pragma unroll
            for (int dd = 0; dd < 16; dd++) {
                float a0 = a_s[dd][ty * 4 + 0];
                float a1 = a_s[dd][ty * 4 + 1];
                float a2 = a_s[dd][ty * 4 + 2];
                float a3 = a_s[dd][ty * 4 + 3];
                float4 b4 = *reinterpret_cast<float4*>(&b_s[dd][tx * 4]);
                acc[0][0] += a0 * b4.x; acc[0][1] += a0 * b4.y; acc[0][2] += a0 * b4.z; acc[0][3] += a0 * b4.w;
                acc[1][0] += a1 * b4.x; acc[1][1] += a1 * b4.y; acc[1][2] += a1 * b4.z; acc[1][3] += a1 * b4.w;
                acc[2][0] += a2 * b4.x; acc[2][1] += a2 * b4.y; acc[2][2] += a2 * b4.z; acc[2][3] += a2 * b4.w;
                acc[3][0] += a3 * b4.x; acc[3][1] += a3 * b4.y; acc[3][2] += a3 * b4.z; acc[3][3] += a3 * b4.w;
            }
            __syncthreads();
        }
        // epilogue: dist = w2 - 2*cross; local argmin over 4 cols (ascending k -> strict <
        // keeps first occurrence), then 64-bit lexicographic atomicMin for row reduce.
        float4 w2v = *reinterpret_cast<const float4*>(&g_w2[nc * 64 + tx * 4]);
        float w2a[4] = {w2v.x, w2v.y, w2v.z, w2v.w};
        int kbase = nc * 64 + tx * 4;
#pragma unroll
        for (int r = 0; r < 4; r++) {
            float best = w2a[0] - 2.f * acc[r][0];
            int bk = kbase;
#pragma unroll
            for (int c = 1; c < 4; c++) {
                float dv = w2a[c] - 2.f * acc[r][c];
                if (dv < best) { best = dv; bk = kbase + c; }
            }
            atomicMin(&keys[ty * 4 + r], packkey(best, bk));
        }
    }
    __syncthreads();
    if (tid < 64) g_idx[m0 + tid] = (int)(keys[tid] & 0xFFFFFFFFu);
}

// ---------------- gather (emb) + decode (recon) ----------------
// grid = 1024 (b,hl), 512 threads, dynamic smem = (32+48)*516 floats
__global__ __launch_bounds__(512) void k_gde(const float* __restrict__ bd,
                                             float* __restrict__ out_emb,
                                             float* __restrict__ out_recon) {
    extern __shared__ float sm[];
    float* zq = sm;              // [32][516]
    float* wds = sm + 32 * 516;  // [48][516]
    __shared__ int karr[32];

    int blk = blockIdx.x;
    int b = blk >> 5;
    int hl = blk & 31;
    int tid = threadIdx.x;

    if (tid < 32) karr[tid] = g_idx[b * NL + hl * 32 + tid];
    for (int e = tid; e < 48 * ND; e += 512) {
        int r = e >> 9, d = e & 511;
        wds[r * 516 + d] = g_wdt[e];
    }
    __syncthreads();
    for (int e = tid; e < 32 * ND; e += 512) {
        int wl = e >> 9, d = e & 511;
        zq[wl * 516 + d] = g_cbt[karr[wl] * ND + d];
    }
    __syncthreads();

    // emb (B,D,L): coalesced 128B rows per d
    float* eb = out_emb + b * (ND * NL) + hl * 32;
    for (int e = tid; e < 16384; e += 512) {
        int d = e >> 5, wl = e & 31;
        eb[d * NL + wl] = zq[wl * 516 + d];
    }

    // decode: 1536 outputs (c,i,col), 512-dot each, + bias + sigmoid
#pragma unroll
    for (int it = 0; it < 3; it++) {
        int o = it * 512 + tid;
        int c = o >> 9;            // == it
        int i = (o >> 7) & 3;
        int col = o & 127;
        int wl = col >> 2, j = col & 3;
        int r = (c * 4 + i) * 4 + j;
        const float* zrow = zq + wl * 516;
        const float* wrow = wds + r * 516;
        float acc = 0.f;
#pragma unroll 8
        for (int d = 0; d < ND; d += 4) {
            float4 zv = *reinterpret_cast<const float4*>(zrow + d);
            float4 wv = *reinterpret_cast<const float4*>(wrow + d);
            acc += zv.x * wv.x + zv.y * wv.y + zv.z * wv.z + zv.w * wv.w;
        }
        acc += bd[c];
        float s = 1.f / (1.f + __expf(-acc));
        out_recon[((b * NC + c) * NH + (4 * hl + i)) * NH + col] = s;
    }
}

// ---------------- launch ----------------
extern "C" void kernel_launch(void* const* d_in, const int* in_sizes, int n_in,
                              void* d_out, int out_size) {
    const float* x  = (const float*)d_in[0];
    const float* We = (const float*)d_in[1];
    const float* be = (const float*)d_in[2];
    const float* Wd = (const float*)d_in[3];
    const float* bd = (const float*)d_in[4];
    const float* cb = (const float*)d_in[5];

    float* out = (float*)d_out;
    float* out_recon = out;
    float* out_ze    = out + RECON_N;
    float* out_emb   = out + RECON_N + ZE_N;

    const int gde_smem = (32 + 48) * 516 * sizeof(float);  // 165120 B
    cudaFuncSetAttribute(k_gde, cudaFuncAttributeMaxDynamicSharedMemorySize, gde_smem);

    k_prep_cbt<<<dim3(16, 16), dim3(32, 8)>>>(cb);
    k_prep_w2<<<4, 128>>>();
    k_prep_wdt<<<96, 256>>>(Wd);
    k_encode<<<1024, 512>>>(x, We, be, out_ze);
    k_argmin<<<512, 256>>>(cb);
    k_gde<<<1024, 512, gde_smem>>>(bd, out_emb, out_recon);
}

// round 5
// speedup vs baseline: 3.4139x; 3.4139x over previous
#include <cuda_runtime.h>
#include <cuda_bf16.h>
#include <cstdint>

// VQ-VAE forward on GB300 (base sm_103 target: mma.sync/ldmatrix/cp.async, no tcgen05).
// Outputs (flattened, in order): recon (32,3,128,128), z_e (32,512,32,32), emb (32,512,32,32)

#define NB 32
#define NC 3
#define NH 128
#define ND 512
#define NK 512
#define NHL 32
#define NL 1024
#define NM (NB * NL)  // 32768

#define RECON_N (32 * 3 * 128 * 128)
#define ZE_N (32 * 512 * 32 * 32)
#define MARGIN 0.75f
#define NSLOT 16

// ---------------- scratch (static device memory; no allocations) ----------------
__device__ __nv_bfloat16 g_zh[NM * ND];   // z_e hi split, row-major (M, D)
__device__ __nv_bfloat16 g_zl[NM * ND];   // z_e lo split
__device__ __nv_bfloat16 g_cbh[NK * ND];  // codebook^T hi split (K, D)
__device__ float g_cbt[NK * ND];          // codebook^T fp32 (K, D)
__device__ float g_w2[NK];                // ||W[:,k]||^2 (fp32 exact)
__device__ float g_wdt[48 * ND];          // decoder weights, spatial flip baked in
__device__ int   g_idx[NM];               // final argmin indices
__device__ unsigned long long g_key[NM];  // pass-1 packed (approx dist, k)
__device__ int g_ccnt[NM];                // candidate counts
__device__ int g_cand[NM * NSLOT];        // candidate k lists

// ---------------- small helpers ----------------
__device__ __forceinline__ unsigned mapf(float x) {
    unsigned u = __float_as_uint(x);
    return (u & 0x80000000u) ? ~u : (u | 0x80000000u);   // order-preserving
}
__device__ __forceinline__ float unmapf(unsigned m) {
    unsigned u = (m & 0x80000000u) ? (m ^ 0x80000000u) : ~m;
    return __uint_as_float(u);
}

#define CP_ASYNC16(smaddr, gptr) \
    asm volatile("cp.async.cg.shared.global [%0], [%1], 16;" :: "r"(smaddr), "l"(gptr))
#define CP_COMMIT() asm volatile("cp.async.commit_group;" ::: "memory")
#define CP_WAIT(n)  asm volatile("cp.async.wait_group %0;" :: "n"(n) : "memory")

__device__ __forceinline__ void ldsm4(uint32_t& r0, uint32_t& r1, uint32_t& r2, uint32_t& r3,
                                      uint32_t addr) {
    asm volatile("ldmatrix.sync.aligned.m8n8.x4.shared.b16 {%0,%1,%2,%3}, [%4];"
                 : "=r"(r0), "=r"(r1), "=r"(r2), "=r"(r3) : "r"(addr));
}
__device__ __forceinline__ void mma16816(float* c, const uint32_t* a, uint32_t b0, uint32_t b1) {
    asm volatile(
        "mma.sync.aligned.m16n8k16.row.col.f32.bf16.bf16.f32 "
        "{%0,%1,%2,%3}, {%4,%5,%6,%7}, {%8,%9}, {%0,%1,%2,%3};"
        : "+f"(c[0]), "+f"(c[1]), "+f"(c[2]), "+f"(c[3])
        : "r"(a[0]), "r"(a[1]), "r"(a[2]), "r"(a[3]), "r"(b0), "r"(b1));
}

// ---------------- prep kernels ----------------
__global__ void k_init() {
    int m = blockIdx.x * 256 + threadIdx.x;   // grid 128 -> 32768
    g_key[m] = 0xFFFFFFFFFFFFFFFFull;
    g_ccnt[m] = 0;
}

__global__ void k_prep_cbt(const float* __restrict__ cb) {
    __shared__ float t[32][33];
    int x = blockIdx.x * 32 + threadIdx.x;
    int y0 = blockIdx.y * 32;
    for (int r = threadIdx.y; r < 32; r += 8)
        t[r][threadIdx.x] = cb[(y0 + r) * NK + x];
    __syncthreads();
    int xo = blockIdx.y * 32 + threadIdx.x;
    int yo = blockIdx.x * 32;
    for (int r = threadIdx.y; r < 32; r += 8)
        g_cbt[(yo + r) * ND + xo] = t[threadIdx.x][r];
}

__global__ void k_prep_w2() {
    int k = blockIdx.x * 128 + threadIdx.x;
    const float* row = g_cbt + k * ND;
    float s = 0.f;
    for (int d = 0; d < ND; d += 4) {
        float4 v = *reinterpret_cast<const float4*>(row + d);
        s += v.x * v.x + v.y * v.y + v.z * v.z + v.w * v.w;
    }
    g_w2[k] = s;
}

__global__ void k_prep_cbsplit() {
    int e = blockIdx.x * 256 + threadIdx.x;   // grid 1024
    g_cbh[e] = __float2bfloat16(g_cbt[e]);
}

__global__ void k_prep_wdt(const float* __restrict__ Wd) {
    int e = blockIdx.x * 256 + threadIdx.x;   // e < 48*512
    int r = e >> 9, d = e & 511;
    int c = r >> 4, i = (r >> 2) & 3, j = r & 3;
    g_wdt[e] = Wd[(c * ND + d) * 16 + (3 - i) * 4 + (3 - j)];
}

// ---------------- encode: patch-embed GEMM + bias + relu ----------------
// grid (1024, 4): x = (b,hl); y: bit0 = position half (16 wl), bit1 = d half (256).
// dynamic smem: patch 16*48 + wsm 256*48 floats.
__global__ __launch_bounds__(256) void k_encode(const float* __restrict__ x,
                                                const float* __restrict__ We,
                                                const float* __restrict__ be,
                                                float* __restrict__ out_ze) {
    extern __shared__ float esm[];
    float* patch = esm;           // [16][48]
    float* wsm = esm + 16 * 48;   // [256][48]
    int blk = blockIdx.x;
    int b = blk >> 5, hl = blk & 31;
    int ph = blockIdx.y & 1, dh = blockIdx.y >> 1;
    int tid = threadIdx.x;

    // stage We half: 256 rows x 48
    for (int e = tid; e < 256 * 48; e += 256)
        wsm[e] = We[dh * (256 * 48) + e];
    // stage input patches: 12 rows x 64 cols
    for (int e = tid; e < 768; e += 256) {
        int row = e >> 6, cc = e & 63;
        int c = row >> 2, i = row & 3;
        float v = x[((b * NC + c) * NH + (4 * hl + i)) * NH + ph * 64 + cc];
        patch[(cc >> 2) * 48 + c * 16 + i * 4 + (cc & 3)] = v;
    }
    __syncthreads();

    int d = dh * 256 + tid;
    float w[48];
#pragma unroll
    for (int q = 0; q < 48; q++) w[q] = wsm[tid * 48 + q];
    float bias = be[d];

    float acc[16];
    int mbase = b * NL + hl * 32 + ph * 16;
#pragma unroll
    for (int pos = 0; pos < 16; pos++) {
        float p0 = bias, p1 = 0.f, p2 = 0.f, p3 = 0.f;
        const float* pp = patch + pos * 48;
#pragma unroll
        for (int q = 0; q < 12; q++) {
            float* dst = (q & 3) == 0 ? &p0 : (q & 3) == 1 ? &p1 : (q & 3) == 2 ? &p2 : &p3;
            *dst += pp[4*q] * w[4*q] + pp[4*q+1] * w[4*q+1] + pp[4*q+2] * w[4*q+2] + pp[4*q+3] * w[4*q+3];
        }
        float v = fmaxf((p0 + p1) + (p2 + p3), 0.f);
        acc[pos] = v;
        __nv_bfloat16 h = __float2bfloat16(v);
        int zi = (mbase + pos) * ND + d;
        g_zh[zi] = h;
        g_zl[zi] = __float2bfloat16(v - __bfloat162float(h));
    }
    float4* o4 = reinterpret_cast<float4*>(out_ze + ((b * ND + d) * NHL + hl) * NHL + ph * 16);
#pragma unroll
    for (int q = 0; q < 4; q++)
        o4[q] = make_float4(acc[4*q], acc[4*q+1], acc[4*q+2], acc[4*q+3]);
}

// ---------------- pass 1: bf16 HMMA GEMM + approx argmin + candidate flagging ----------------
// grid (256, 4): 128-row m-tile x 128-code n-tile. BK=64, double-buffered cp.async.
// smem stage: [128][72] bf16 (144B row pitch, pad 8) for A and B, 2 stages = 73728 B.
#define STG_BYTES 18432
#define NN_SMEM (4 * STG_BYTES)

__device__ __forceinline__ void nn_fill(uint32_t smb, int stg, int kc, int m0, int n0, int tid) {
    uint32_t ab = smb + stg * STG_BYTES;
    uint32_t bb = smb + 2 * STG_BYTES + stg * STG_BYTES;
#pragma unroll
    for (int i = 0; i < 4; i++) {
        int u = i * 256 + tid;            // 0..1023
        int r = u >> 3, cg = u & 7;
        CP_ASYNC16(ab + r * 144 + cg * 16, g_zh + (m0 + r) * ND + kc * 64 + cg * 8);
    }
#pragma unroll
    for (int i = 0; i < 4; i++) {
        int u = i * 256 + tid;
        int r = u >> 3, cg = u & 7;
        CP_ASYNC16(bb + r * 144 + cg * 16, g_cbh + (n0 + r) * ND + kc * 64 + cg * 8);
    }
}

__global__ __launch_bounds__(256, 2) void k_nn() {
    extern __shared__ __align__(16) char nsm[];
    __shared__ float w2s[128];
    __shared__ unsigned rmin[128];
    int tid = threadIdx.x;
    int lane = tid & 31, wrp = tid >> 5;
    int wm = wrp & 3, wn = wrp >> 2;      // 4 x 2 warp grid; warp tile 32(m) x 64(n)
    int m0 = blockIdx.x * 128, n0 = blockIdx.y * 128;
    uint32_t smb = (uint32_t)__cvta_generic_to_shared(nsm);

    if (tid < 128) { w2s[tid] = g_w2[n0 + tid]; rmin[tid] = 0xFFFFFFFFu; }

    float cfr[2][8][4];
#pragma unroll
    for (int mt = 0; mt < 2; mt++)
#pragma unroll
        for (int nt = 0; nt < 8; nt++)
#pragma unroll
            for (int q = 0; q < 4; q++) cfr[mt][nt][q] = 0.f;

    nn_fill(smb, 0, 0, m0, n0, tid);
    CP_COMMIT();

    for (int kc = 0; kc < 8; kc++) {
        if (kc < 7) { nn_fill(smb, (kc + 1) & 1, kc + 1, m0, n0, tid); CP_COMMIT(); CP_WAIT(1); }
        else        { CP_WAIT(0); }
        __syncthreads();
        uint32_t sa = smb + (kc & 1) * STG_BYTES;
        uint32_t sb = smb + 2 * STG_BYTES + (kc & 1) * STG_BYTES;
#pragma unroll
        for (int ks = 0; ks < 4; ks++) {
            uint32_t afr[2][4];
#pragma unroll
            for (int mt = 0; mt < 2; mt++) {
                int r = wm * 32 + mt * 16 + ((lane >> 3) & 1) * 8 + (lane & 7);
                int cb = ks * 32 + (lane >> 4) * 16;
                ldsm4(afr[mt][0], afr[mt][1], afr[mt][2], afr[mt][3], sa + r * 144 + cb);
            }
            uint32_t bfr[8][2];
#pragma unroll
            for (int p = 0; p < 4; p++) {
                int r = wn * 64 + p * 16 + (lane >> 4) * 8 + (lane & 7);
                int cb = ks * 32 + ((lane >> 3) & 1) * 16;
                uint32_t b0, b1, b2, b3;
                ldsm4(b0, b1, b2, b3, sb + r * 144 + cb);
                bfr[2*p][0] = b0; bfr[2*p][1] = b1; bfr[2*p+1][0] = b2; bfr[2*p+1][1] = b3;
            }
#pragma unroll
            for (int mt = 0; mt < 2; mt++)
#pragma unroll
                for (int nt = 0; nt < 8; nt++)
                    mma16816(cfr[mt][nt], afr[mt], bfr[nt][0], bfr[nt][1]);
        }
        __syncthreads();
    }

    // epilogue phase 1: per-row block min (smem) + global packed atomicMin
#pragma unroll
    for (int mt = 0; mt < 2; mt++) {
#pragma unroll
        for (int h = 0; h < 2; h++) {
            int lr = wm * 32 + mt * 16 + (lane >> 2) + h * 8;
            unsigned long long best = 0xFFFFFFFFFFFFFFFFull;
#pragma unroll
            for (int nt = 0; nt < 8; nt++)
#pragma unroll
                for (int c2 = 0; c2 < 2; c2++) {
                    int kl = wn * 64 + nt * 8 + (lane & 3) * 2 + c2;
                    float dist = w2s[kl] - 2.f * cfr[mt][nt][h * 2 + c2];
                    unsigned long long key =
                        ((unsigned long long)mapf(dist) << 32) | (unsigned)(n0 + kl);
                    if (key < best) best = key;
                }
            unsigned long long o1 = __shfl_xor_sync(0xffffffffu, best, 1);
            if (o1 < best) best = o1;
            unsigned long long o2 = __shfl_xor_sync(0xffffffffu, best, 2);
            if (o2 < best) best = o2;
            if ((lane & 3) == 0) {
                atomicMin(&rmin[lr], (unsigned)(best >> 32));
                atomicMin(&g_key[m0 + lr], best);
            }
        }
    }
    __syncthreads();

    // epilogue phase 2: flag candidates within MARGIN of block row-min
#pragma unroll
    for (int mt = 0; mt < 2; mt++) {
#pragma unroll
        for (int h = 0; h < 2; h++) {
            int lr = wm * 32 + mt * 16 + (lane >> 2) + h * 8;
            float thr = unmapf(rmin[lr]) + MARGIN;
#pragma unroll
            for (int nt = 0; nt < 8; nt++)
#pragma unroll
                for (int c2 = 0; c2 < 2; c2++) {
                    int kl = wn * 64 + nt * 8 + (lane & 3) * 2 + c2;
                    float dist = w2s[kl] - 2.f * cfr[mt][nt][h * 2 + c2];
                    if (dist <= thr) {
                        int pos = atomicAdd(&g_ccnt[m0 + lr], 1);
                        if (pos < NSLOT) g_cand[(m0 + lr) * NSLOT + pos] = n0 + kl;
                    }
                }
        }
    }
}

// ---------------- pass 2: exact fp32 rescore of candidates ----------------
// one warp per row; grid 4096 x 256
__global__ __launch_bounds__(256) void k_rescore() {
    int tid = threadIdx.x, lane = tid & 31;
    int m = blockIdx.x * 8 + (tid >> 5);

    float4 z[4];
#pragma unroll
    for (int t = 0; t < 4; t++) {
        int d = t * 128 + lane * 4;
        uint2 hh = *reinterpret_cast<const uint2*>(g_zh + m * ND + d);
        uint2 ll = *reinterpret_cast<const uint2*>(g_zl + m * ND + d);
        __nv_bfloat162 h0 = *reinterpret_cast<__nv_bfloat162*>(&hh.x);
        __nv_bfloat162 h1 = *reinterpret_cast<__nv_bfloat162*>(&hh.y);
        __nv_bfloat162 l0 = *reinterpret_cast<__nv_bfloat162*>(&ll.x);
        __nv_bfloat162 l1 = *reinterpret_cast<__nv_bfloat162*>(&ll.y);
        z[t].x = __bfloat162float(h0.x) + __bfloat162float(l0.x);
        z[t].y = __bfloat162float(h0.y) + __bfloat162float(l0.y);
        z[t].z = __bfloat162float(h1.x) + __bfloat162float(l1.x);
        z[t].w = __bfloat162float(h1.y) + __bfloat162float(l1.y);
    }
    int cnt = g_ccnt[m]; if (cnt > NSLOT) cnt = NSLOT;
    int kstar = (int)(g_key[m] & 0xFFFFFFFFu);
    unsigned long long best = 0xFFFFFFFFFFFFFFFFull;
    for (int ci = -1; ci < cnt; ci++) {
        int k = (ci < 0) ? kstar : g_cand[m * NSLOT + ci];
        float s = 0.f;
#pragma unroll
        for (int t = 0; t < 4; t++) {
            float4 cv = *reinterpret_cast<const float4*>(g_cbt + k * ND + t * 128 + lane * 4);
            s += z[t].x * cv.x + z[t].y * cv.y + z[t].z * cv.z + z[t].w * cv.w;
        }
#pragma unroll
        for (int off = 16; off > 0; off >>= 1) s += __shfl_xor_sync(0xffffffffu, s, off);
        float dist = g_w2[k] - 2.f * s;
        unsigned long long key = ((unsigned long long)mapf(dist) << 32) | (unsigned)k;
        if (key < best) best = key;
    }
    if (lane == 0) g_idx[m] = (int)(best & 0xFFFFFFFFu);
}

// ---------------- gather (emb) + decode (recon) ----------------
// dynamic smem: zq[32][517] + wds[48][517] + part[3072]
#define GDE_SMEM ((80 * 517 + 3072) * 4)
__global__ __launch_bounds__(512) void k_gde(const float* __restrict__ bd,
                                             float* __restrict__ out_emb,
                                             float* __restrict__ out_recon) {
    extern __shared__ float smf[];
    float* zq = smf;               // [32][517]
    float* wds = smf + 32 * 517;   // [48][517]
    float* part = smf + 80 * 517;  // [32*48][2]
    __shared__ int karr[32];

    int blk = blockIdx.x;
    int b = blk >> 5, hl = blk & 31;
    int tid = threadIdx.x;

    if (tid < 32) karr[tid] = g_idx[b * NL + hl * 32 + tid];
    for (int e = tid; e < 48 * ND; e += 512) {
        int r = e >> 9, d = e & 511;
        wds[r * 517 + d] = g_wdt[e];
    }
    __syncthreads();
    for (int e = tid; e < 32 * ND; e += 512) {
        int wl = e >> 9, d = e & 511;
        zq[wl * 517 + d] = g_cbt[karr[wl] * ND + d];
    }
    __syncthreads();

    // emb output (B,D,L)
    float* eb = out_emb + b * (ND * NL) + hl * 32;
    for (int e = tid; e < 16384; e += 512) {
        int d = e >> 5, wl = e & 31;
        eb[d * NL + wl] = zq[wl * 517 + d];
    }

    // decode partials: warp w: wl-group = w&7 (4 wl), d-slice = w>>3 (256 d).
    // lane: wli = lane>>3, rr = lane&7; 6 outputs rr+8t.
    {
        int wrp = tid >> 5, lane = tid & 31;
        int wlg = wrp & 7, ds = wrp >> 3;
        int wl = wlg * 4 + (lane >> 3);
        int rr = lane & 7;
        float acc[6] = {0.f, 0.f, 0.f, 0.f, 0.f, 0.f};
        const float* zr = zq + wl * 517 + ds * 256;
        const float* wb = wds + rr * 517 + ds * 256;
#pragma unroll 4
        for (int d = 0; d < 256; d++) {
            float zz = zr[d];
#pragma unroll
            for (int t = 0; t < 6; t++)
                acc[t] += zz * wb[t * 8 * 517 + d];
        }
#pragma unroll
        for (int t = 0; t < 6; t++)
            part[(wl * 48 + rr + 8 * t) * 2 + ds] = acc[t];
    }
    __syncthreads();

    // finalize 1536 outputs: sum 2 partials + bias + sigmoid
#pragma unroll
    for (int it = 0; it < 3; it++) {
        int o = it * 512 + tid;
        int wlo = o / 48;
        int ro = o - wlo * 48;
        float v = part[(wlo * 48 + ro) * 2] + part[(wlo * 48 + ro) * 2 + 1];
        int cc = ro >> 4, ii = (ro >> 2) & 3, jj = ro & 3;
        v += bd[cc];
        float s = 1.f / (1.f + __expf(-v));
        out_recon[((b * NC + cc) * NH + (4 * hl + ii)) * NH + wlo * 4 + jj] = s;
    }
}

// ---------------- launch ----------------
extern "C" void kernel_launch(void* const* d_in, const int* in_sizes, int n_in,
                              void* d_out, int out_size) {
    const float* x  = (const float*)d_in[0];
    const float* We = (const float*)d_in[1];
    const float* be = (const float*)d_in[2];
    const float* Wd = (const float*)d_in[3];
    const float* bd = (const float*)d_in[4];
    const float* cb = (const float*)d_in[5];

    float* out = (float*)d_out;
    float* out_recon = out;
    float* out_ze    = out + RECON_N;
    float* out_emb   = out + RECON_N + ZE_N;

    const int enc_smem = (16 * 48 + 256 * 48) * sizeof(float);  // 52224
    cudaFuncSetAttribute(k_encode, cudaFuncAttributeMaxDynamicSharedMemorySize, enc_smem);
    cudaFuncSetAttribute(k_nn, cudaFuncAttributeMaxDynamicSharedMemorySize, NN_SMEM);
    cudaFuncSetAttribute(k_gde, cudaFuncAttributeMaxDynamicSharedMemorySize, GDE_SMEM);

    k_init<<<128, 256>>>();
    k_prep_cbt<<<dim3(16, 16), dim3(32, 8)>>>(cb);
    k_prep_w2<<<4, 128>>>();
    k_prep_cbsplit<<<1024, 256>>>();
    k_prep_wdt<<<96, 256>>>(Wd);
    k_encode<<<dim3(1024, 4), 256, enc_smem>>>(x, We, be, out_ze);
    k_nn<<<dim3(256, 4), 256, NN_SMEM>>>();
    k_rescore<<<4096, 256>>>();
    k_gde<<<1024, 512, GDE_SMEM>>>(bd, out_emb, out_recon);
}

// round 9
// speedup vs baseline: 3.9494x; 1.1569x over previous
#include <cuda_runtime.h>
#include <cuda_bf16.h>
#include <cstdint>

// VQ-VAE forward on GB300 (base sm_103 target: mma.sync/ldmatrix/cp.async).
// Outputs (flattened, in order): recon (32,3,128,128), z_e (32,512,32,32), emb (32,512,32,32)

#define NB 32
#define NC 3
#define NH 128
#define ND 512
#define NK 512
#define NHL 32
#define NL 1024
#define NM (NB * NL)  // 32768

#define RECON_N (32 * 3 * 128 * 128)
#define ZE_N (32 * 512 * 32 * 32)
#define MARGIN 0.45f
#define NSLOT 16

// ---------------- scratch (static device memory; no allocations) ----------------
__device__ __nv_bfloat16 g_zh[NM * ND];   // z_e hi split, row-major (M, D)
__device__ __nv_bfloat16 g_zl[NM * ND];   // z_e lo split
__device__ __nv_bfloat16 g_cbh[NK * ND];  // codebook^T bf16 (K, D)
__device__ float g_cbt[NK * ND];          // codebook^T fp32 (K, D)
__device__ float g_w2[NK];                // ||W[:,k]||^2 (fp32 exact)
__device__ float g_wdt[48 * ND];          // decoder weights, spatial flip baked in
__device__ int   g_idx[NM];               // final argmin indices
__device__ unsigned long long g_key[NM];  // pass-1 packed (approx dist, k)
__device__ int g_ccnt[NM];                // candidate counts
__device__ int g_cand[NM * NSLOT];        // candidate k lists

// ---------------- small helpers ----------------
__device__ __forceinline__ unsigned mapf(float x) {
    unsigned u = __float_as_uint(x);
    return (u & 0x80000000u) ? ~u : (u | 0x80000000u);   // order-preserving
}
__device__ __forceinline__ float unmapf(unsigned m) {
    unsigned u = (m & 0x80000000u) ? (m ^ 0x80000000u) : ~m;
    return __uint_as_float(u);
}

#define CP_ASYNC16(smaddr, gptr) \
    asm volatile("cp.async.cg.shared.global [%0], [%1], 16;" :: "r"(smaddr), "l"(gptr))
#define CP_COMMIT() asm volatile("cp.async.commit_group;" ::: "memory")
#define CP_WAIT(n)  asm volatile("cp.async.wait_group %0;" :: "n"(n) : "memory")

__device__ __forceinline__ void ldsm4(uint32_t& r0, uint32_t& r1, uint32_t& r2, uint32_t& r3,
                                      uint32_t addr) {
    asm volatile("ldmatrix.sync.aligned.m8n8.x4.shared.b16 {%0,%1,%2,%3}, [%4];"
                 : "=r"(r0), "=r"(r1), "=r"(r2), "=r"(r3) : "r"(addr));
}
__device__ __forceinline__ void mma16816(float* c, const uint32_t* a, uint32_t b0, uint32_t b1) {
    asm volatile(
        "mma.sync.aligned.m16n8k16.row.col.f32.bf16.bf16.f32 "
        "{%0,%1,%2,%3}, {%4,%5,%6,%7}, {%8,%9}, {%0,%1,%2,%3};"
        : "+f"(c[0]), "+f"(c[1]), "+f"(c[2]), "+f"(c[3])
        : "r"(a[0]), "r"(a[1]), "r"(a[2]), "r"(a[3]), "r"(b0), "r"(b1));
}

// ---------------- prep 1: codebook transpose (D,K)->(K,D) + bf16 split ----------------
__global__ void k_prep_cbt(const float* __restrict__ cb) {
    __shared__ float t[32][33];
    int x = blockIdx.x * 32 + threadIdx.x;
    int y0 = blockIdx.y * 32;
    for (int r = threadIdx.y; r < 32; r += 8)
        t[r][threadIdx.x] = cb[(y0 + r) * NK + x];
    __syncthreads();
    int xo = blockIdx.y * 32 + threadIdx.x;
    int yo = blockIdx.x * 32;
    for (int r = threadIdx.y; r < 32; r += 8) {
        float v = t[threadIdx.x][r];
        g_cbt[(yo + r) * ND + xo] = v;
        g_cbh[(yo + r) * ND + xo] = __float2bfloat16(v);
    }
}

// ---------------- prep 2 (fused): wdt / w2 / key-init, range-partitioned ----------------
__global__ void k_prep2(const float* __restrict__ Wd) {
    int blk = blockIdx.x, tid = threadIdx.x;
    if (blk < 96) {
        int e = blk * 256 + tid;   // 48*512 = 24576
        int r = e >> 9, d = e & 511;
        int c = r >> 4, i = (r >> 2) & 3, j = r & 3;
        g_wdt[e] = Wd[(c * ND + d) * 16 + (3 - i) * 4 + (3 - j)];
    } else if (blk < 98) {
        int k = (blk - 96) * 256 + tid;
        const float* row = g_cbt + k * ND;
        float s = 0.f;
        for (int d = 0; d < ND; d += 4) {
            float4 v = *reinterpret_cast<const float4*>(row + d);
            s += v.x * v.x + v.y * v.y + v.z * v.z + v.w * v.w;
        }
        g_w2[k] = s;
    } else {
        int m = (blk - 98) * 256 + tid;   // 128 blocks -> 32768
        g_key[m] = 0xFFFFFFFFFFFFFFFFull;
        g_ccnt[m] = 0;
    }
}

// ---------------- encode: patch-embed GEMM + bias + relu ----------------
// grid (1024, 4): x = (b,hl); y: bit0 = position half (16 wl), bit1 = d half (256).
__global__ __launch_bounds__(256) void k_encode(const float* __restrict__ x,
                                                const float* __restrict__ We,
                                                const float* __restrict__ be,
                                                float* __restrict__ out_ze) {
    extern __shared__ float esm[];
    float* patch = esm;           // [16][48]
    float* wsm = esm + 16 * 48;   // [256][48]
    int blk = blockIdx.x;
    int b = blk >> 5, hl = blk & 31;
    int ph = blockIdx.y & 1, dh = blockIdx.y >> 1;
    int tid = threadIdx.x;

    for (int e = tid; e < 256 * 48; e += 256)
        wsm[e] = We[dh * (256 * 48) + e];
    for (int e = tid; e < 768; e += 256) {
        int row = e >> 6, cc = e & 63;
        int c = row >> 2, i = row & 3;
        float v = x[((b * NC + c) * NH + (4 * hl + i)) * NH + ph * 64 + cc];
        patch[(cc >> 2) * 48 + c * 16 + i * 4 + (cc & 3)] = v;
    }
    __syncthreads();

    int d = dh * 256 + tid;
    float w[48];
#pragma unroll
    for (int q = 0; q < 48; q++) w[q] = wsm[tid * 48 + q];
    float bias = be[d];

    float acc[16];
    int mbase = b * NL + hl * 32 + ph * 16;
#pragma unroll
    for (int pos = 0; pos < 16; pos++) {
        float p0 = bias, p1 = 0.f, p2 = 0.f, p3 = 0.f;
        const float* pp = patch + pos * 48;
#pragma unroll
        for (int q = 0; q < 12; q++) {
            float* dst = (q & 3) == 0 ? &p0 : (q & 3) == 1 ? &p1 : (q & 3) == 2 ? &p2 : &p3;
            *dst += pp[4*q] * w[4*q] + pp[4*q+1] * w[4*q+1] + pp[4*q+2] * w[4*q+2] + pp[4*q+3] * w[4*q+3];
        }
        float v = fmaxf((p0 + p1) + (p2 + p3), 0.f);
        acc[pos] = v;
        __nv_bfloat16 h = __float2bfloat16(v);
        int zi = (mbase + pos) * ND + d;
        g_zh[zi] = h;
        g_zl[zi] = __float2bfloat16(v - __bfloat162float(h));
    }
    float4* o4 = reinterpret_cast<float4*>(out_ze + ((b * ND + d) * NHL + hl) * NHL + ph * 16);
#pragma unroll
    for (int q = 0; q < 4; q++)
        o4[q] = make_float4(acc[4*q], acc[4*q+1], acc[4*q+2], acc[4*q+3]);
}

// ---------------- pass 1: bf16 HMMA GEMM + approx argmin + candidate flagging ----------------
#define STG_BYTES 18432
#define NN_SMEM (4 * STG_BYTES)

__device__ __forceinline__ void nn_fill(uint32_t smb, int stg, int kc, int m0, int n0, int tid) {
    uint32_t ab = smb + stg * STG_BYTES;
    uint32_t bb = smb + 2 * STG_BYTES + stg * STG_BYTES;
#pragma unroll
    for (int i = 0; i < 4; i++) {
        int u = i * 256 + tid;
        int r = u >> 3, cg = u & 7;
        CP_ASYNC16(ab + r * 144 + cg * 16, g_zh + (m0 + r) * ND + kc * 64 + cg * 8);
    }
#pragma unroll
    for (int i = 0; i < 4; i++) {
        int u = i * 256 + tid;
        int r = u >> 3, cg = u & 7;
        CP_ASYNC16(bb + r * 144 + cg * 16, g_cbh + (n0 + r) * ND + kc * 64 + cg * 8);
    }
}

__global__ __launch_bounds__(256, 2) void k_nn() {
    extern __shared__ __align__(16) char nsm[];
    __shared__ float w2s[128];
    __shared__ unsigned rmin[128];
    int tid = threadIdx.x;
    int lane = tid & 31, wrp = tid >> 5;
    int wm = wrp & 3, wn = wrp >> 2;
    int m0 = blockIdx.x * 128, n0 = blockIdx.y * 128;
    uint32_t smb = (uint32_t)__cvta_generic_to_shared(nsm);

    if (tid < 128) { w2s[tid] = g_w2[n0 + tid]; rmin[tid] = 0xFFFFFFFFu; }

    float cfr[2][8][4];
#pragma unroll
    for (int mt = 0; mt < 2; mt++)
#pragma unroll
        for (int nt = 0; nt < 8; nt++)
#pragma unroll
            for (int q = 0; q < 4; q++) cfr[mt][nt][q] = 0.f;

    nn_fill(smb, 0, 0, m0, n0, tid);
    CP_COMMIT();

    for (int kc = 0; kc < 8; kc++) {
        if (kc < 7) { nn_fill(smb, (kc + 1) & 1, kc + 1, m0, n0, tid); CP_COMMIT(); CP_WAIT(1); }
        else        { CP_WAIT(0); }
        __syncthreads();
        uint32_t sa = smb + (kc & 1) * STG_BYTES;
        uint32_t sb = smb + 2 * STG_BYTES + (kc & 1) * STG_BYTES;
#pragma unroll
        for (int ks = 0; ks < 4; ks++) {
            uint32_t afr[2][4];
#pragma unroll
            for (int mt = 0; mt < 2; mt++) {
                int r = wm * 32 + mt * 16 + ((lane >> 3) & 1) * 8 + (lane & 7);
                int cb = ks * 32 + (lane >> 4) * 16;
                ldsm4(afr[mt][0], afr[mt][1], afr[mt][2], afr[mt][3], sa + r * 144 + cb);
            }
            uint32_t bfr[8][2];
#pragma unroll
            for (int p = 0; p < 4; p++) {
                int r = wn * 64 + p * 16 + (lane >> 4) * 8 + (lane & 7);
                int cb = ks * 32 + ((lane >> 3) & 1) * 16;
                uint32_t b0, b1, b2, b3;
                ldsm4(b0, b1, b2, b3, sb + r * 144 + cb);
                bfr[2*p][0] = b0; bfr[2*p][1] = b1; bfr[2*p+1][0] = b2; bfr[2*p+1][1] = b3;
            }
#pragma unroll
            for (int mt = 0; mt < 2; mt++)
#pragma unroll
                for (int nt = 0; nt < 8; nt++)
                    mma16816(cfr[mt][nt], afr[mt], bfr[nt][0], bfr[nt][1]);
        }
        __syncthreads();
    }

#pragma unroll
    for (int mt = 0; mt < 2; mt++) {
#pragma unroll
        for (int h = 0; h < 2; h++) {
            int lr = wm * 32 + mt * 16 + (lane >> 2) + h * 8;
            unsigned long long best = 0xFFFFFFFFFFFFFFFFull;
#pragma unroll
            for (int nt = 0; nt < 8; nt++)
#pragma unroll
                for (int c2 = 0; c2 < 2; c2++) {
                    int kl = wn * 64 + nt * 8 + (lane & 3) * 2 + c2;
                    float dist = w2s[kl] - 2.f * cfr[mt][nt][h * 2 + c2];
                    unsigned long long key =
                        ((unsigned long long)mapf(dist) << 32) | (unsigned)(n0 + kl);
                    if (key < best) best = key;
                }
            unsigned long long o1 = __shfl_xor_sync(0xffffffffu, best, 1);
            if (o1 < best) best = o1;
            unsigned long long o2 = __shfl_xor_sync(0xffffffffu, best, 2);
            if (o2 < best) best = o2;
            if ((lane & 3) == 0) {
                atomicMin(&rmin[lr], (unsigned)(best >> 32));
                atomicMin(&g_key[m0 + lr], best);
            }
        }
    }
    __syncthreads();

#pragma unroll
    for (int mt = 0; mt < 2; mt++) {
#pragma unroll
        for (int h = 0; h < 2; h++) {
            int lr = wm * 32 + mt * 16 + (lane >> 2) + h * 8;
            float thr = unmapf(rmin[lr]) + MARGIN;
#pragma unroll
            for (int nt = 0; nt < 8; nt++)
#pragma unroll
                for (int c2 = 0; c2 < 2; c2++) {
                    int kl = wn * 64 + nt * 8 + (lane & 3) * 2 + c2;
                    float dist = w2s[kl] - 2.f * cfr[mt][nt][h * 2 + c2];
                    if (dist <= thr) {
                        int pos = atomicAdd(&g_ccnt[m0 + lr], 1);
                        if (pos < NSLOT) g_cand[(m0 + lr) * NSLOT + pos] = n0 + kl;
                    }
                }
        }
    }
}

// ---------------- pass 2: exact fp32 rescore of candidates ----------------
__global__ __launch_bounds__(256) void k_rescore() {
    int tid = threadIdx.x, lane = tid & 31;
    int m = blockIdx.x * 8 + (tid >> 5);

    float4 z[4];
#pragma unroll
    for (int t = 0; t < 4; t++) {
        int d = t * 128 + lane * 4;
        uint2 hh = *reinterpret_cast<const uint2*>(g_zh + m * ND + d);
        uint2 ll = *reinterpret_cast<const uint2*>(g_zl + m * ND + d);
        __nv_bfloat162 h0 = *reinterpret_cast<__nv_bfloat162*>(&hh.x);
        __nv_bfloat162 h1 = *reinterpret_cast<__nv_bfloat162*>(&hh.y);
        __nv_bfloat162 l0 = *reinterpret_cast<__nv_bfloat162*>(&ll.x);
        __nv_bfloat162 l1 = *reinterpret_cast<__nv_bfloat162*>(&ll.y);
        z[t].x = __bfloat162float(h0.x) + __bfloat162float(l0.x);
        z[t].y = __bfloat162float(h0.y) + __bfloat162float(l0.y);
        z[t].z = __bfloat162float(h1.x) + __bfloat162float(l1.x);
        z[t].w = __bfloat162float(h1.y) + __bfloat162float(l1.y);
    }
    int cnt = g_ccnt[m]; if (cnt > NSLOT) cnt = NSLOT;
    int kstar = (int)(g_key[m] & 0xFFFFFFFFu);
    unsigned long long best = 0xFFFFFFFFFFFFFFFFull;
    for (int ci = -1; ci < cnt; ci++) {
        int k = (ci < 0) ? kstar : g_cand[m * NSLOT + ci];
        float s = 0.f;
#pragma unroll
        for (int t = 0; t < 4; t++) {
            float4 cv = *reinterpret_cast<const float4*>(g_cbt + k * ND + t * 128 + lane * 4);
            s += z[t].x * cv.x + z[t].y * cv.y + z[t].z * cv.z + z[t].w * cv.w;
        }
#pragma unroll
        for (int off = 16; off > 0; off >>= 1) s += __shfl_xor_sync(0xffffffffu, s, off);
        float dist = g_w2[k] - 2.f * s;
        unsigned long long key = ((unsigned long long)mapf(dist) << 32) | (unsigned)k;
        if (key < best) best = key;
    }
    if (lane == 0) g_idx[m] = (int)(best & 0xFFFFFFFFu);
}

// ---------------- gather (emb) + decode (recon) ----------------
// zq pitch 517 (conflict-free broadcast), wds pitch 524 (6*524 mod 32 == 8 ->
// the 4 rgL row-groups land on banks {0,8,16,24}+dq: fully conflict-free).
#define ZQP 517
#define WDP 524
#define GDE_SMEM ((32 * ZQP + 48 * WDP + 1536) * 4)
__global__ __launch_bounds__(512) void k_gde(const float* __restrict__ bd,
                                             float* __restrict__ out_emb,
                                             float* __restrict__ out_recon) {
    extern __shared__ float smf[];
    float* zq = smf;                       // [32][ZQP]
    float* wds = smf + 32 * ZQP;           // [48][WDP]
    float* part = smf + 32 * ZQP + 48 * WDP;  // [32*48]
    __shared__ int karr[32];

    int blk = blockIdx.x;
    int b = blk >> 5, hl = blk & 31;
    int tid = threadIdx.x;

    if (tid < 32) karr[tid] = g_idx[b * NL + hl * 32 + tid];
    for (int e = tid; e < 48 * ND; e += 512) {
        int r = e >> 9, d = e & 511;
        wds[r * WDP + d] = g_wdt[e];
    }
    __syncthreads();
    for (int e = tid; e < 32 * ND; e += 512) {
        int wl = e >> 9, d = e & 511;
        zq[wl * ZQP + d] = g_cbt[karr[wl] * ND + d];
    }
    __syncthreads();

    // emb output (B,D,L)
    float* eb = out_emb + b * (ND * NL) + hl * 32;
    for (int e = tid; e < 16384; e += 512) {
        int d = e >> 5, wl = e & 31;
        eb[d * NL + wl] = zq[wl * ZQP + d];
    }

    // decode: register-tiled 4(wl) x 6(r) per thread, d interleaved stride 8.
    {
        int lane = tid & 31, w = tid >> 5;
        int dq = lane & 7;
        int rg = ((lane >> 3) & 3) + 4 * (w & 1);   // 0..7 -> rows rg*6..rg*6+5
        int wlb = (w >> 1) * 4;                     // 0,4,...,28
        float acc[4][6];
#pragma unroll
        for (int j = 0; j < 4; j++)
#pragma unroll
            for (int s = 0; s < 6; s++) acc[j][s] = 0.f;

        const float* z0p = zq + (wlb + 0) * ZQP;
        const float* z1p = zq + (wlb + 1) * ZQP;
        const float* z2p = zq + (wlb + 2) * ZQP;
        const float* z3p = zq + (wlb + 3) * ZQP;
        const float* wp = wds + (rg * 6) * WDP;
#pragma unroll 4
        for (int i = 0; i < 64; i++) {
            int d = dq + 8 * i;
            float z0 = z0p[d], z1 = z1p[d], z2 = z2p[d], z3 = z3p[d];
#pragma unroll
            for (int s = 0; s < 6; s++) {
                float wv = wp[s * WDP + d];
                acc[0][s] += z0 * wv;
                acc[1][s] += z1 * wv;
                acc[2][s] += z2 * wv;
                acc[3][s] += z3 * wv;
            }
        }
        // reduce over dq lanes (xor 1,2,4)
#pragma unroll
        for (int off = 1; off < 8; off <<= 1)
#pragma unroll
            for (int j = 0; j < 4; j++)
#pragma unroll
                for (int s = 0; s < 6; s++)
                    acc[j][s] += __shfl_xor_sync(0xffffffffu, acc[j][s], off);
        if (dq == 0) {
#pragma unroll
            for (int j = 0; j < 4; j++)
#pragma unroll
                for (int s = 0; s < 6; s++)
                    part[(wlb + j) * 48 + rg * 6 + s] = acc[j][s];
        }
    }
    __syncthreads();

    // finalize 1536 outputs: + bias + sigmoid, coalesced writes
#pragma unroll
    for (int it = 0; it < 3; it++) {
        int o = it * 512 + tid;
        int wlo = o / 48;
        int ro = o - wlo * 48;
        float v = part[wlo * 48 + ro];
        int cc = ro >> 4, ii = (ro >> 2) & 3, jj = ro & 3;
        v += bd[cc];
        float s = 1.f / (1.f + __expf(-v));
        out_recon[((b * NC + cc) * NH + (4 * hl + ii)) * NH + wlo * 4 + jj] = s;
    }
}

// ---------------- launch ----------------
extern "C" void kernel_launch(void* const* d_in, const int* in_sizes, int n_in,
                              void* d_out, int out_size) {
    const float* x  = (const float*)d_in[0];
    const float* We = (const float*)d_in[1];
    const float* be = (const float*)d_in[2];
    const float* Wd = (const float*)d_in[3];
    const float* bd = (const float*)d_in[4];
    const float* cb = (const float*)d_in[5];

    float* out = (float*)d_out;
    float* out_recon = out;
    float* out_ze    = out + RECON_N;
    float* out_emb   = out + RECON_N + ZE_N;

    const int enc_smem = (16 * 48 + 256 * 48) * sizeof(float);  // 52224
    cudaFuncSetAttribute(k_encode, cudaFuncAttributeMaxDynamicSharedMemorySize, enc_smem);
    cudaFuncSetAttribute(k_nn, cudaFuncAttributeMaxDynamicSharedMemorySize, NN_SMEM);
    cudaFuncSetAttribute(k_gde, cudaFuncAttributeMaxDynamicSharedMemorySize, GDE_SMEM);

    k_prep_cbt<<<dim3(16, 16), dim3(32, 8)>>>(cb);
    k_prep2<<<226, 256>>>(Wd);
    k_encode<<<dim3(1024, 4), 256, enc_smem>>>(x, We, be, out_ze);
    k_nn<<<dim3(256, 4), 256, NN_SMEM>>>();
    k_rescore<<<4096, 256>>>();
    k_gde<<<1024, 512, GDE_SMEM>>>(bd, out_emb, out_recon);
}

// round 10
// speedup vs baseline: 4.1299x; 1.0457x over previous
#include <cuda_runtime.h>
#include <cuda_bf16.h>
#include <cstdint>

// VQ-VAE forward on GB300 (base sm_103 target: mma.sync/ldmatrix/cp.async).
// Outputs (flattened, in order): recon (32,3,128,128), z_e (32,512,32,32), emb (32,512,32,32)

#define NB 32
#define NC 3
#define NH 128
#define ND 512
#define NK 512
#define NHL 32
#define NL 1024
#define NM (NB * NL)  // 32768

#define RECON_N (32 * 3 * 128 * 128)
#define ZE_N (32 * 512 * 32 * 32)
#define MARGIN 0.45f
#define NSLOT 16

// ---------------- scratch (static device memory; no allocations) ----------------
__device__ __nv_bfloat16 g_zh[NM * ND];   // z_e hi split, row-major (M, D)
__device__ __nv_bfloat16 g_zl[NM * ND];   // z_e lo split
__device__ __nv_bfloat16 g_cbh[NK * ND];  // codebook^T bf16 (K, D)
__device__ float g_cbt[NK * ND];          // codebook^T fp32 (K, D)
__device__ float g_w2[NK];                // ||W[:,k]||^2 (fp32 exact)
__device__ float g_wdt[48 * ND];          // decoder weights, spatial flip baked in
__device__ int   g_idx[NM];               // final argmin indices
__device__ unsigned long long g_key[NM];  // pass-1 packed (approx dist, k)
__device__ int g_ccnt[NM];                // candidate counts
__device__ unsigned long long g_cand[NM * NSLOT];  // candidate packed (dist, k)

// ---------------- small helpers ----------------
__device__ __forceinline__ unsigned mapf(float x) {
    unsigned u = __float_as_uint(x);
    return (u & 0x80000000u) ? ~u : (u | 0x80000000u);   // order-preserving
}
__device__ __forceinline__ float unmapf(unsigned m) {
    unsigned u = (m & 0x80000000u) ? (m ^ 0x80000000u) : ~m;
    return __uint_as_float(u);
}

#define CP_ASYNC16(smaddr, gptr) \
    asm volatile("cp.async.cg.shared.global [%0], [%1], 16;" :: "r"(smaddr), "l"(gptr))
#define CP_COMMIT() asm volatile("cp.async.commit_group;" ::: "memory")
#define CP_WAIT(n)  asm volatile("cp.async.wait_group %0;" :: "n"(n) : "memory")

__device__ __forceinline__ void ldsm4(uint32_t& r0, uint32_t& r1, uint32_t& r2, uint32_t& r3,
                                      uint32_t addr) {
    asm volatile("ldmatrix.sync.aligned.m8n8.x4.shared.b16 {%0,%1,%2,%3}, [%4];"
                 : "=r"(r0), "=r"(r1), "=r"(r2), "=r"(r3) : "r"(addr));
}
__device__ __forceinline__ void mma16816(float* c, const uint32_t* a, uint32_t b0, uint32_t b1) {
    asm volatile(
        "mma.sync.aligned.m16n8k16.row.col.f32.bf16.bf16.f32 "
        "{%0,%1,%2,%3}, {%4,%5,%6,%7}, {%8,%9}, {%0,%1,%2,%3};"
        : "+f"(c[0]), "+f"(c[1]), "+f"(c[2]), "+f"(c[3])
        : "r"(a[0]), "r"(a[1]), "r"(a[2]), "r"(a[3]), "r"(b0), "r"(b1));
}

// ---------------- prep 1: codebook transpose (D,K)->(K,D) + bf16 split ----------------
__global__ void k_prep_cbt(const float* __restrict__ cb) {
    __shared__ float t[32][33];
    int x = blockIdx.x * 32 + threadIdx.x;
    int y0 = blockIdx.y * 32;
    for (int r = threadIdx.y; r < 32; r += 8)
        t[r][threadIdx.x] = cb[(y0 + r) * NK + x];
    __syncthreads();
    int xo = blockIdx.y * 32 + threadIdx.x;
    int yo = blockIdx.x * 32;
    for (int r = threadIdx.y; r < 32; r += 8) {
        float v = t[threadIdx.x][r];
        g_cbt[(yo + r) * ND + xo] = v;
        g_cbh[(yo + r) * ND + xo] = __float2bfloat16(v);
    }
}

// ---------------- prep 2 (fused): wdt / w2 / key-init, range-partitioned ----------------
__global__ void k_prep2(const float* __restrict__ Wd) {
    int blk = blockIdx.x, tid = threadIdx.x;
    if (blk < 96) {
        int e = blk * 256 + tid;   // 48*512 = 24576
        int r = e >> 9, d = e & 511;
        int c = r >> 4, i = (r >> 2) & 3, j = r & 3;
        g_wdt[e] = Wd[(c * ND + d) * 16 + (3 - i) * 4 + (3 - j)];
    } else if (blk < 98) {
        int k = (blk - 96) * 256 + tid;
        const float* row = g_cbt + k * ND;
        float s = 0.f;
        for (int d = 0; d < ND; d += 4) {
            float4 v = *reinterpret_cast<const float4*>(row + d);
            s += v.x * v.x + v.y * v.y + v.z * v.z + v.w * v.w;
        }
        g_w2[k] = s;
    } else {
        int m = (blk - 98) * 256 + tid;   // 128 blocks -> 32768
        g_key[m] = 0xFFFFFFFFFFFFFFFFull;
        g_ccnt[m] = 0;
    }
}

// ---------------- encode: patch-embed GEMM + bias + relu ----------------
// grid (1024, 4): x = (b,hl); y: bit0 = position half (16 wl), bit1 = d half (256).
__global__ __launch_bounds__(256) void k_encode(const float* __restrict__ x,
                                                const float* __restrict__ We,
                                                const float* __restrict__ be,
                                                float* __restrict__ out_ze) {
    extern __shared__ float esm[];
    float* patch = esm;           // [16][48]
    float* wsm = esm + 16 * 48;   // [256][48]
    int blk = blockIdx.x;
    int b = blk >> 5, hl = blk & 31;
    int ph = blockIdx.y & 1, dh = blockIdx.y >> 1;
    int tid = threadIdx.x;

    for (int e = tid; e < 256 * 48; e += 256)
        wsm[e] = We[dh * (256 * 48) + e];
    for (int e = tid; e < 768; e += 256) {
        int row = e >> 6, cc = e & 63;
        int c = row >> 2, i = row & 3;
        float v = x[((b * NC + c) * NH + (4 * hl + i)) * NH + ph * 64 + cc];
        patch[(cc >> 2) * 48 + c * 16 + i * 4 + (cc & 3)] = v;
    }
    __syncthreads();

    int d = dh * 256 + tid;
    float w[48];
#pragma unroll
    for (int q = 0; q < 48; q++) w[q] = wsm[tid * 48 + q];
    float bias = be[d];

    float acc[16];
    int mbase = b * NL + hl * 32 + ph * 16;
#pragma unroll
    for (int pos = 0; pos < 16; pos++) {
        float p0 = bias, p1 = 0.f, p2 = 0.f, p3 = 0.f;
        const float* pp = patch + pos * 48;
#pragma unroll
        for (int q = 0; q < 12; q++) {
            float* dst = (q & 3) == 0 ? &p0 : (q & 3) == 1 ? &p1 : (q & 3) == 2 ? &p2 : &p3;
            *dst += pp[4*q] * w[4*q] + pp[4*q+1] * w[4*q+1] + pp[4*q+2] * w[4*q+2] + pp[4*q+3] * w[4*q+3];
        }
        float v = fmaxf((p0 + p1) + (p2 + p3), 0.f);
        acc[pos] = v;
        __nv_bfloat16 h = __float2bfloat16(v);
        int zi = (mbase + pos) * ND + d;
        g_zh[zi] = h;
        g_zl[zi] = __float2bfloat16(v - __bfloat162float(h));
    }
    float4* o4 = reinterpret_cast<float4*>(out_ze + ((b * ND + d) * NHL + hl) * NHL + ph * 16);
#pragma unroll
    for (int q = 0; q < 4; q++)
        o4[q] = make_float4(acc[4*q], acc[4*q+1], acc[4*q+2], acc[4*q+3]);
}

// ---------------- pass 1: bf16 HMMA GEMM + approx argmin + candidate flagging ----------------
// 3-stage cp.async pipeline: stage = A[128][144B] + B[128][144B] = 36864 B.
#define STG 36864
#define NN_SMEM (3 * STG)   // 110592 B; 2 blocks/SM = 216 KB

__global__ __launch_bounds__(256, 2) void k_nn() {
    extern __shared__ __align__(16) char nsm[];
    __shared__ float w2s[128];
    __shared__ unsigned rmin[128];
    int tid = threadIdx.x;
    int lane = tid & 31, wrp = tid >> 5;
    int wm = wrp & 3, wn = wrp >> 2;
    int m0 = blockIdx.x * 128, n0 = blockIdx.y * 128;
    uint32_t smb = (uint32_t)__cvta_generic_to_shared(nsm);

    // fill bases (folded: per cp.async only immediate-style adds remain)
    int tr = tid >> 3, cg = tid & 7;
    uint32_t so0 = (uint32_t)(tr * 144 + cg * 16);
    const __nv_bfloat16* pa0 = g_zh + (m0 + tr) * ND + cg * 8;
    const __nv_bfloat16* pb0 = g_cbh + (n0 + tr) * ND + cg * 8;

    auto fill = [&](int stage, int kc) {
        uint32_t ab = smb + stage * STG + so0;
        uint32_t bb = ab + 18432;
        const __nv_bfloat16* ap = pa0 + kc * 64;
        const __nv_bfloat16* bp = pb0 + kc * 64;
#pragma unroll
        for (int i = 0; i < 4; i++) CP_ASYNC16(ab + i * 4608, ap + i * (32 * ND));
#pragma unroll
        for (int i = 0; i < 4; i++) CP_ASYNC16(bb + i * 4608, bp + i * (32 * ND));
    };

    if (tid < 128) { w2s[tid] = g_w2[n0 + tid]; rmin[tid] = 0xFFFFFFFFu; }

    float cfr[2][8][4];
#pragma unroll
    for (int mt = 0; mt < 2; mt++)
#pragma unroll
        for (int nt = 0; nt < 8; nt++)
#pragma unroll
            for (int q = 0; q < 4; q++) cfr[mt][nt][q] = 0.f;

    fill(0, 0); CP_COMMIT();
    fill(1, 1); CP_COMMIT();

    for (int kc = 0; kc < 8; kc++) {
        if (kc < 6) { CP_WAIT(1); } else { CP_WAIT(0); }
        __syncthreads();   // stage kc ready; all warps done with stage (kc-1)
        if (kc < 6) { fill((kc + 2) % 3, kc + 2); CP_COMMIT(); }
        uint32_t sa = smb + (kc % 3) * STG;
        uint32_t sb = sa + 18432;
#pragma unroll
        for (int ks = 0; ks < 4; ks++) {
            uint32_t afr[2][4];
#pragma unroll
            for (int mt = 0; mt < 2; mt++) {
                int r = wm * 32 + mt * 16 + ((lane >> 3) & 1) * 8 + (lane & 7);
                int cb = ks * 32 + (lane >> 4) * 16;
                ldsm4(afr[mt][0], afr[mt][1], afr[mt][2], afr[mt][3], sa + r * 144 + cb);
            }
            uint32_t bfr[8][2];
#pragma unroll
            for (int p = 0; p < 4; p++) {
                int r = wn * 64 + p * 16 + (lane >> 4) * 8 + (lane & 7);
                int cb = ks * 32 + ((lane >> 3) & 1) * 16;
                uint32_t b0, b1, b2, b3;
                ldsm4(b0, b1, b2, b3, sb + r * 144 + cb);
                bfr[2*p][0] = b0; bfr[2*p][1] = b1; bfr[2*p+1][0] = b2; bfr[2*p+1][1] = b3;
            }
#pragma unroll
            for (int mt = 0; mt < 2; mt++)
#pragma unroll
                for (int nt = 0; nt < 8; nt++)
                    mma16816(cfr[mt][nt], afr[mt], bfr[nt][0], bfr[nt][1]);
        }
    }

    // epilogue phase 1: per-row block min (smem) + global packed atomicMin
#pragma unroll
    for (int mt = 0; mt < 2; mt++) {
#pragma unroll
        for (int h = 0; h < 2; h++) {
            int lr = wm * 32 + mt * 16 + (lane >> 2) + h * 8;
            unsigned long long best = 0xFFFFFFFFFFFFFFFFull;
#pragma unroll
            for (int nt = 0; nt < 8; nt++)
#pragma unroll
                for (int c2 = 0; c2 < 2; c2++) {
                    int kl = wn * 64 + nt * 8 + (lane & 3) * 2 + c2;
                    float dist = w2s[kl] - 2.f * cfr[mt][nt][h * 2 + c2];
                    unsigned long long key =
                        ((unsigned long long)mapf(dist) << 32) | (unsigned)(n0 + kl);
                    if (key < best) best = key;
                }
            unsigned long long o1 = __shfl_xor_sync(0xffffffffu, best, 1);
            if (o1 < best) best = o1;
            unsigned long long o2 = __shfl_xor_sync(0xffffffffu, best, 2);
            if (o2 < best) best = o2;
            if ((lane & 3) == 0) {
                atomicMin(&rmin[lr], (unsigned)(best >> 32));
                atomicMin(&g_key[m0 + lr], best);
            }
        }
    }
    __syncthreads();

    // epilogue phase 2: flag candidates (store packed key) within MARGIN of block row-min
#pragma unroll
    for (int mt = 0; mt < 2; mt++) {
#pragma unroll
        for (int h = 0; h < 2; h++) {
            int lr = wm * 32 + mt * 16 + (lane >> 2) + h * 8;
            float thr = unmapf(rmin[lr]) + MARGIN;
#pragma unroll
            for (int nt = 0; nt < 8; nt++)
#pragma unroll
                for (int c2 = 0; c2 < 2; c2++) {
                    int kl = wn * 64 + nt * 8 + (lane & 3) * 2 + c2;
                    float dist = w2s[kl] - 2.f * cfr[mt][nt][h * 2 + c2];
                    if (dist <= thr) {
                        int pos = atomicAdd(&g_ccnt[m0 + lr], 1);
                        if (pos < NSLOT)
                            g_cand[(m0 + lr) * NSLOT + pos] =
                                ((unsigned long long)mapf(dist) << 32) | (unsigned)(n0 + kl);
                    }
                }
        }
    }
}

// ---------------- pass 2: exact fp32 rescore (fast path: approx winner unambiguous) ----------------
__global__ __launch_bounds__(256) void k_rescore() {
    int tid = threadIdx.x, lane = tid & 31;
    int m = blockIdx.x * 8 + (tid >> 5);

    unsigned long long gkey = g_key[m];
    float amin = unmapf((unsigned)(gkey >> 32));
    int kstar = (int)(gkey & 0xFFFFFFFFu);
    int cnt = g_ccnt[m]; if (cnt > NSLOT) cnt = NSLOT;

    unsigned long long ck = 0xFFFFFFFFFFFFFFFFull;
    if (lane < cnt) ck = g_cand[m * NSLOT + lane];
    bool qual = (lane < cnt) && (ck != gkey) &&
                (unmapf((unsigned)(ck >> 32)) <= amin + MARGIN);
    unsigned bal = __ballot_sync(0xffffffffu, qual);
    if (bal == 0) {   // no challenger within global margin: approx winner is exact
        if (lane == 0) g_idx[m] = kstar;
        return;
    }

    // slow path: reconstruct z (fp32 from hi+lo) and exactly rescore kstar + challengers
    float4 z[4];
#pragma unroll
    for (int t = 0; t < 4; t++) {
        int d = t * 128 + lane * 4;
        uint2 hh = *reinterpret_cast<const uint2*>(g_zh + m * ND + d);
        uint2 ll = *reinterpret_cast<const uint2*>(g_zl + m * ND + d);
        __nv_bfloat162 h0 = *reinterpret_cast<__nv_bfloat162*>(&hh.x);
        __nv_bfloat162 h1 = *reinterpret_cast<__nv_bfloat162*>(&hh.y);
        __nv_bfloat162 l0 = *reinterpret_cast<__nv_bfloat162*>(&ll.x);
        __nv_bfloat162 l1 = *reinterpret_cast<__nv_bfloat162*>(&ll.y);
        z[t].x = __bfloat162float(h0.x) + __bfloat162float(l0.x);
        z[t].y = __bfloat162float(h0.y) + __bfloat162float(l0.y);
        z[t].z = __bfloat162float(h1.x) + __bfloat162float(l1.x);
        z[t].w = __bfloat162float(h1.y) + __bfloat162float(l1.y);
    }
    unsigned mycand = (unsigned)(ck & 0xFFFFFFFFu);
    unsigned long long best = 0xFFFFFFFFFFFFFFFFull;
    int k = kstar;
    unsigned rem = bal;
    for (;;) {
        float s = 0.f;
#pragma unroll
        for (int t = 0; t < 4; t++) {
            float4 cv = *reinterpret_cast<const float4*>(g_cbt + k * ND + t * 128 + lane * 4);
            s += z[t].x * cv.x + z[t].y * cv.y + z[t].z * cv.z + z[t].w * cv.w;
        }
#pragma unroll
        for (int off = 16; off > 0; off >>= 1) s += __shfl_xor_sync(0xffffffffu, s, off);
        float dist = g_w2[k] - 2.f * s;
        unsigned long long key = ((unsigned long long)mapf(dist) << 32) | (unsigned)k;
        if (key < best) best = key;
        if (!rem) break;
        int src = __ffs(rem) - 1;
        rem &= rem - 1;
        k = (int)__shfl_sync(0xffffffffu, mycand, src);
    }
    if (lane == 0) g_idx[m] = (int)(best & 0xFFFFFFFFu);
}

// ---------------- gather (emb) + decode (recon) ----------------
// zq pitch 517 (conflict-free broadcast), wds pitch 524 (conflict-free row groups).
#define ZQP 517
#define WDP 524
#define GDE_SMEM ((32 * ZQP + 48 * WDP + 1536) * 4)
__global__ __launch_bounds__(512) void k_gde(const float* __restrict__ bd,
                                             float* __restrict__ out_emb,
                                             float* __restrict__ out_recon) {
    extern __shared__ float smf[];
    float* zq = smf;                       // [32][ZQP]
    float* wds = smf + 32 * ZQP;           // [48][WDP]
    float* part = smf + 32 * ZQP + 48 * WDP;  // [32*48]
    __shared__ int karr[32];

    int blk = blockIdx.x;
    int b = blk >> 5, hl = blk & 31;
    int tid = threadIdx.x;

    if (tid < 32) karr[tid] = g_idx[b * NL + hl * 32 + tid];
    for (int e = tid; e < 48 * ND; e += 512) {
        int r = e >> 9, d = e & 511;
        wds[r * WDP + d] = g_wdt[e];
    }
    __syncthreads();
    for (int e = tid; e < 32 * ND; e += 512) {
        int wl = e >> 9, d = e & 511;
        zq[wl * ZQP + d] = g_cbt[karr[wl] * ND + d];
    }
    __syncthreads();

    // emb output (B,D,L)
    float* eb = out_emb + b * (ND * NL) + hl * 32;
    for (int e = tid; e < 16384; e += 512) {
        int d = e >> 5, wl = e & 31;
        eb[d * NL + wl] = zq[wl * ZQP + d];
    }

    // decode: register-tiled 4(wl) x 6(r) per thread, d interleaved stride 8.
    {
        int lane = tid & 31, w = tid >> 5;
        int dq = lane & 7;
        int rg = ((lane >> 3) & 3) + 4 * (w & 1);
        int wlb = (w >> 1) * 4;
        float acc[4][6];
#pragma unroll
        for (int j = 0; j < 4; j++)
#pragma unroll
            for (int s = 0; s < 6; s++) acc[j][s] = 0.f;

        const float* z0p = zq + (wlb + 0) * ZQP;
        const float* z1p = zq + (wlb + 1) * ZQP;
        const float* z2p = zq + (wlb + 2) * ZQP;
        const float* z3p = zq + (wlb + 3) * ZQP;
        const float* wp = wds + (rg * 6) * WDP;
#pragma unroll 4
        for (int i = 0; i < 64; i++) {
            int d = dq + 8 * i;
            float z0 = z0p[d], z1 = z1p[d], z2 = z2p[d], z3 = z3p[d];
#pragma unroll
            for (int s = 0; s < 6; s++) {
                float wv = wp[s * WDP + d];
                acc[0][s] += z0 * wv;
                acc[1][s] += z1 * wv;
                acc[2][s] += z2 * wv;
                acc[3][s] += z3 * wv;
            }
        }
#pragma unroll
        for (int off = 1; off < 8; off <<= 1)
#pragma unroll
            for (int j = 0; j < 4; j++)
#pragma unroll
                for (int s = 0; s < 6; s++)
                    acc[j][s] += __shfl_xor_sync(0xffffffffu, acc[j][s], off);
        if (dq == 0) {
#pragma unroll
            for (int j = 0; j < 4; j++)
#pragma unroll
                for (int s = 0; s < 6; s++)
                    part[(wlb + j) * 48 + rg * 6 + s] = acc[j][s];
        }
    }
    __syncthreads();

#pragma unroll
    for (int it = 0; it < 3; it++) {
        int o = it * 512 + tid;
        int wlo = o / 48;
        int ro = o - wlo * 48;
        float v = part[wlo * 48 + ro];
        int cc = ro >> 4, ii = (ro >> 2) & 3, jj = ro & 3;
        v += bd[cc];
        float s = 1.f / (1.f + __expf(-v));
        out_recon[((b * NC + cc) * NH + (4 * hl + ii)) * NH + wlo * 4 + jj] = s;
    }
}

// ---------------- launch ----------------
extern "C" void kernel_launch(void* const* d_in, const int* in_sizes, int n_in,
                              void* d_out, int out_size) {
    const float* x  = (const float*)d_in[0];
    const float* We = (const float*)d_in[1];
    const float* be = (const float*)d_in[2];
    const float* Wd = (const float*)d_in[3];
    const float* bd = (const float*)d_in[4];
    const float* cb = (const float*)d_in[5];

    float* out = (float*)d_out;
    float* out_recon = out;
    float* out_ze    = out + RECON_N;
    float* out_emb   = out + RECON_N + ZE_N;

    const int enc_smem = (16 * 48 + 256 * 48) * sizeof(float);  // 52224
    cudaFuncSetAttribute(k_encode, cudaFuncAttributeMaxDynamicSharedMemorySize, enc_smem);
    cudaFuncSetAttribute(k_nn, cudaFuncAttributeMaxDynamicSharedMemorySize, NN_SMEM);
    cudaFuncSetAttribute(k_gde, cudaFuncAttributeMaxDynamicSharedMemorySize, GDE_SMEM);

    k_prep_cbt<<<dim3(16, 16), dim3(32, 8)>>>(cb);
    k_prep2<<<226, 256>>>(Wd);
    k_encode<<<dim3(1024, 4), 256, enc_smem>>>(x, We, be, out_ze);
    k_nn<<<dim3(256, 4), 256, NN_SMEM>>>();
    k_rescore<<<4096, 256>>>();
    k_gde<<<1024, 512, GDE_SMEM>>>(bd, out_emb, out_recon);
}